// round 8
// baseline (speedup 1.0000x reference)
#include <cuda_runtime.h>
#include <cuda_fp16.h>
#include <math.h>
#include <stdint.h>

#define BB 2
#define SS 2048
#define DDIM 1024
#define HH 16
#define DK 64
#define MROWS 4096   // B*S

typedef __half h16;

// ---------------- device scratch ----------------
__device__ __align__(16) h16 g_hhi[MROWS*DDIM];
__device__ __align__(16) h16 g_hlo[MROWS*DDIM];
__device__ __align__(16) h16 g_Wthi[4*DDIM*DDIM];   // [slot][n][k]
__device__ __align__(16) h16 g_Wtlo[4*DDIM*DDIM];
__device__ __align__(16) h16 g_Qhi[MROWS*DDIM];
__device__ __align__(16) h16 g_Qlo[MROWS*DDIM];
__device__ __align__(16) h16 g_Khi[MROWS*DDIM];
__device__ __align__(16) h16 g_Klo[MROWS*DDIM];
__device__ __align__(16) h16 g_Vhi[MROWS*DDIM];
__device__ __align__(16) h16 g_Vlo[MROWS*DDIM];
__device__ __align__(16) h16 g_chi[MROWS*DDIM];
__device__ __align__(16) h16 g_clo[MROWS*DDIM];
__device__ __align__(16) float g_bd[HH*4096];

// ---------------- low-level helpers ----------------
__device__ __forceinline__ uint32_t smem_u32(const void* p) {
    uint32_t a;
    asm("{ .reg .u64 t; cvta.to.shared.u64 t, %1; cvt.u32.u64 %0, t; }" : "=r"(a) : "l"(p));
    return a;
}
__device__ __forceinline__ void sts16(uint32_t a, unsigned short v) {
    asm volatile("st.shared.u16 [%0], %1;" :: "r"(a), "h"(v));
}
__device__ __forceinline__ void cp16(uint32_t dst, const void* src) {
    asm volatile("cp.async.ca.shared.global [%0], [%1], 16;" :: "r"(dst), "l"(src));
}
#define CP_COMMIT() asm volatile("cp.async.commit_group;" ::: "memory")
#define CP_WAIT(N)  asm volatile("cp.async.wait_group %0;" :: "n"(N) : "memory")

__device__ __forceinline__ void ldsm4(uint32_t* r, uint32_t addr) {
    asm volatile("ldmatrix.sync.aligned.m8n8.x4.shared.b16 {%0,%1,%2,%3}, [%4];"
        : "=r"(r[0]), "=r"(r[1]), "=r"(r[2]), "=r"(r[3]) : "r"(addr));
}
__device__ __forceinline__ void mma_f16(float* c, const uint32_t* a, uint32_t b0, uint32_t b1) {
    asm volatile("mma.sync.aligned.m16n8k16.row.col.f32.f16.f16.f32 "
        "{%0,%1,%2,%3}, {%4,%5,%6,%7}, {%8,%9}, {%0,%1,%2,%3};"
        : "+f"(c[0]), "+f"(c[1]), "+f"(c[2]), "+f"(c[3])
        : "r"(a[0]), "r"(a[1]), "r"(a[2]), "r"(a[3]), "r"(b0), "r"(b1));
}
__device__ __forceinline__ uint32_t h2u(__half2 v) {
    union { __half2 h; uint32_t u; } c; c.h = v; return c.u;
}
// pack (a,b) to fp16x2 hi, residual to lo
__device__ __forceinline__ uint32_t packpair(float a, float b, uint32_t& lo) {
    __half2 h = __floats2half2_rn(a, b);
    float2 f = __half22float2(h);
    lo = h2u(__floats2half2_rn(a - f.x, b - f.y));
    return h2u(h);
}
__device__ __forceinline__ uint32_t packh(float a, float b) {
    return h2u(__floats2half2_rn(a, b));
}

// ---------------- bias precompute ----------------
__global__ void bias_precompute_kernel(const float* __restrict__ table) {
    int idx = blockIdx.x * blockDim.x + threadIdx.x;
    if (idx >= 4096) return;
    int delta = idx - 2047;
    int bucket = (delta > 0) ? 16 : 0;
    int rp = delta < 0 ? -delta : delta;
    int add;
    if (rp < 8) add = rp;
    else {
        float v = logf((float)rp / 8.0f) / logf(16.0f) * 8.0f;
        int vi = 8 + (int)v;
        add = vi < 15 ? vi : 15;
    }
    bucket += add;
    #pragma unroll
    for (int h = 0; h < HH; h++)
        g_bd[h*4096 + idx] = table[bucket*HH + h];
}

__global__ void bias_out_kernel(float* __restrict__ out) {
    long long i4 = (long long)blockIdx.x * blockDim.x + threadIdx.x;
    const long long per_h = (long long)SS * SS / 4;
    int h = (int)(i4 / per_h);
    long long rem = i4 - (long long)h * per_h;
    int q = (int)(rem / (SS/4));
    int k4 = (int)(rem % (SS/4)) * 4;
    const float* row = g_bd + h*4096 + (k4 - q + 2047);
    reinterpret_cast<float4*>(out)[i4] = make_float4(row[0], row[1], row[2], row[3]);
}

// ---------------- fp32 -> fp16 hi/lo split (hidden) ----------------
__global__ void split_kernel(const float* __restrict__ X,
                             h16* __restrict__ Hi, h16* __restrict__ Lo, int n4) {
    int i = blockIdx.x * blockDim.x + threadIdx.x;
    if (i >= n4) return;
    float4 v = reinterpret_cast<const float4*>(X)[i];
    float xs[4] = {v.x, v.y, v.z, v.w};
    ushort4 ho, lo;
    unsigned short* hp = &ho.x;
    unsigned short* lp = &lo.x;
    #pragma unroll
    for (int j = 0; j < 4; j++) {
        h16 h = __float2half_rn(xs[j]);
        float hf = __half2float(h);
        h16 l = __float2half_rn(xs[j] - hf);
        hp[j] = __half_as_ushort(h);
        lp[j] = __half_as_ushort(l);
    }
    reinterpret_cast<ushort4*>(Hi)[i] = ho;
    reinterpret_cast<ushort4*>(Lo)[i] = lo;
}

// ---------------- fused W transpose + split (z = slot 0..3) ----------------
__global__ void wsplit4_kernel(const float* __restrict__ W0, const float* __restrict__ W1,
                               const float* __restrict__ W2, const float* __restrict__ W3,
                               h16* __restrict__ ThiB, h16* __restrict__ TloB) {
    __shared__ float ts[32][33];
    int z = blockIdx.z;
    const float* W = (z == 0) ? W0 : (z == 1) ? W1 : (z == 2) ? W2 : W3;
    h16* Thi = ThiB + (size_t)z * DDIM * DDIM;
    h16* Tlo = TloB + (size_t)z * DDIM * DDIM;
    int bx = blockIdx.x * 32, by = blockIdx.y * 32;
    int tx = threadIdx.x, ty = threadIdx.y;
    #pragma unroll
    for (int j = 0; j < 32; j += 8)
        ts[ty + j][tx] = W[(size_t)(by + ty + j) * 1024 + bx + tx];
    __syncthreads();
    #pragma unroll
    for (int j = 0; j < 32; j += 8) {
        int n = bx + ty + j, k = by + tx;
        float x = ts[tx][ty + j];
        h16 h = __float2half_rn(x);
        float hf = __half2float(h);
        h16 l = __float2half_rn(x - hf);
        Thi[(size_t)n * 1024 + k] = h;
        Tlo[(size_t)n * 1024 + k] = l;
    }
}

// ---------------- mma.sync GEMM, fp16 hi/lo, fused over z ----------------
// wantf32=0 (QKV): 3-pass (ah*bh + ah*bl + al*bh), outputs hi/lo fp16.
// wantf32=1 (Wo):  2-pass (ah*bh + ah*bl), outputs fp32.
#define GT 10240
#define GBUF 40960
#define GEMM_SMEM (2*GBUF)

__global__ __launch_bounds__(256) void gemm_mma_kernel(
    const h16* __restrict__ Ahi, const h16* __restrict__ Alo,
    const h16* __restrict__ WhiB, const h16* __restrict__ WloB,
    h16* __restrict__ o0h, h16* __restrict__ o0l,
    h16* __restrict__ o1h, h16* __restrict__ o1l,
    h16* __restrict__ o2h, h16* __restrict__ o2l,
    float* __restrict__ Cf, int wantf32)
{
    extern __shared__ char smem[];
    uint32_t sb = smem_u32(smem);
    int tid = threadIdx.x, w = tid >> 5, lane = tid & 31;
    int g = lane >> 2, t2 = (lane & 3) * 2;
    int wm = w >> 2, wn = w & 3;
    int m0 = blockIdx.y * 128, n0 = blockIdx.x * 128;
    int z = blockIdx.z;
    const h16* Bhi = WhiB + (size_t)z * DDIM * DDIM;
    const h16* Blo = WloB + (size_t)z * DDIM * DDIM;
    h16* Chi = (z == 0) ? o0h : (z == 1) ? o1h : o2h;
    h16* Clo = (z == 0) ? o0l : (z == 1) ? o1l : o2l;

    int lm_a  = lane & 15;
    int lm_ak = ((lane >> 4) & 1) * 8;
    int lm_bn = ((lane >> 4) & 1) * 8 + (lane & 7);
    int lm_bk = ((lane >> 3) & 1) * 8;

    float c[4][4][4];
    #pragma unroll
    for (int i = 0; i < 4; i++)
        #pragma unroll
        for (int j = 0; j < 4; j++)
            #pragma unroll
            for (int r = 0; r < 4; r++) c[i][j][r] = 0.f;

    auto load_chunk = [&](int ch, int buf) {
        int k0 = ch * 32;
        uint32_t base = sb + (uint32_t)buf * GBUF;
        #pragma unroll
        for (int t = 0; t < 2; t++) {
            int idx = tid + t * 256;
            int row = idx >> 2, seg = idx & 3;
            uint32_t doff = (uint32_t)(row * 40 + seg * 8) * 2;
            size_t aoff = (size_t)(m0 + row) * 1024 + k0 + seg * 8;
            size_t boff = (size_t)(n0 + row) * 1024 + k0 + seg * 8;
            cp16(base + doff,          Ahi + aoff);
            cp16(base + GT + doff,     Alo + aoff);
            cp16(base + 2*GT + doff,   Bhi + boff);
            cp16(base + 3*GT + doff,   Blo + boff);
        }
    };

    load_chunk(0, 0); CP_COMMIT();
    for (int ch = 0; ch < 32; ch++) {
        int buf = ch & 1;
        if (ch + 1 < 32) { load_chunk(ch + 1, buf ^ 1); CP_COMMIT(); CP_WAIT(1); }
        else CP_WAIT(0);
        __syncthreads();
        uint32_t base = sb + (uint32_t)buf * GBUF;
        #pragma unroll
        for (int ks = 0; ks < 2; ks++) {
            uint32_t ah[4][4], al[4][4];
            #pragma unroll
            for (int mt = 0; mt < 4; mt++) {
                uint32_t ab = base + (uint32_t)((wm*64 + mt*16 + lm_a)*40 + ks*16 + lm_ak)*2;
                ldsm4(ah[mt], ab);
                if (!wantf32) ldsm4(al[mt], ab + GT);
            }
            uint32_t bh[2][4], bl[2][4];
            #pragma unroll
            for (int np = 0; np < 2; np++) {
                uint32_t bb = base + 2*GT +
                    (uint32_t)((wn*32 + np*16 + lm_bn)*40 + ks*16 + lm_bk)*2;
                ldsm4(bh[np], bb);
                ldsm4(bl[np], bb + GT);
            }
            #pragma unroll
            for (int nt = 0; nt < 4; nt++) {
                uint32_t bh0 = bh[nt>>1][(nt&1)*2], bh1 = bh[nt>>1][(nt&1)*2+1];
                uint32_t bl0 = bl[nt>>1][(nt&1)*2], bl1 = bl[nt>>1][(nt&1)*2+1];
                #pragma unroll
                for (int mt = 0; mt < 4; mt++) {
                    mma_f16(c[mt][nt], ah[mt], bh0, bh1);
                    mma_f16(c[mt][nt], ah[mt], bl0, bl1);
                    if (!wantf32) mma_f16(c[mt][nt], al[mt], bh0, bh1);
                }
            }
        }
        __syncthreads();
    }

    #pragma unroll
    for (int mt = 0; mt < 4; mt++) {
        #pragma unroll
        for (int nt = 0; nt < 4; nt++) {
            int m = m0 + wm*64 + mt*16 + g;
            int n = n0 + wn*32 + nt*8 + t2;
            float* cr = c[mt][nt];
            if (wantf32) {
                *reinterpret_cast<float2*>(&Cf[(size_t)m*1024 + n])     = make_float2(cr[0], cr[1]);
                *reinterpret_cast<float2*>(&Cf[(size_t)(m+8)*1024 + n]) = make_float2(cr[2], cr[3]);
            } else {
                uint32_t lo0, lo1;
                uint32_t h0 = packpair(cr[0], cr[1], lo0);
                uint32_t h1 = packpair(cr[2], cr[3], lo1);
                *reinterpret_cast<uint32_t*>(&Chi[(size_t)m*1024 + n])     = h0;
                *reinterpret_cast<uint32_t*>(&Clo[(size_t)m*1024 + n])     = lo0;
                *reinterpret_cast<uint32_t*>(&Chi[(size_t)(m+8)*1024 + n]) = h1;
                *reinterpret_cast<uint32_t*>(&Clo[(size_t)(m+8)*1024 + n]) = lo1;
            }
        }
    }
}

// ---------------- flash attention: QK 3-pass, PV 2-pass ----------------
#define SQHI 0
#define SQLO 18432
#define SKHI 36864
#define SKLO 55296
#define SVTHI 73728
#define SVTLO 91136
#define SBIAS 108544
#define FL_SMEM (SBIAS + 8704)

__global__ __launch_bounds__(256) void flash_mma_kernel() {
    extern __shared__ char smem[];
    uint32_t sb = smem_u32(smem);
    float* sbias = reinterpret_cast<float*>(smem + SBIAS);

    int tid = threadIdx.x, w = tid >> 5, lane = tid & 31;
    int g = lane >> 2, t2 = (lane & 3) * 2;
    int q0 = blockIdx.x * 128;
    int bh = blockIdx.y;
    int h = bh & 15, b = bh >> 4;
    int hbase = h * 64;
    size_t qrow0 = (size_t)(b * SS + q0);

    int lm_a  = lane & 15;
    int lm_ak = ((lane >> 4) & 1) * 8;
    int lm_bn = ((lane >> 4) & 1) * 8 + (lane & 7);
    int lm_bk = ((lane >> 3) & 1) * 8;

    #pragma unroll
    for (int t = 0; t < 4; t++) {
        int idx = tid + t * 256;
        int row = idx >> 3, seg = idx & 7;
        uint32_t doff = (uint32_t)(row * 72 + seg * 8) * 2;
        size_t goff = (qrow0 + row) * 1024 + hbase + seg * 8;
        cp16(sb + SQHI + doff, g_Qhi + goff);
        cp16(sb + SQLO + doff, g_Qlo + goff);
    }
    CP_COMMIT();
    for (int i = tid; i < 2176; i += 256) {
        int gidx = (1920 - q0) + i;
        float v = 0.f;
        if (gidx >= 0 && gidx < 4096) v = g_bd[h*4096 + gidx];
        sbias[i] = v;
    }

    float acc[8][4];
    #pragma unroll
    for (int i = 0; i < 8; i++)
        #pragma unroll
        for (int r = 0; r < 4; r++) acc[i][r] = 0.f;
    float mrow[2] = {-1e30f, -1e30f};
    float lrow[2] = {0.f, 0.f};

    for (int kt = 0; kt < 16; kt++) {
        __syncthreads();
        int kb = kt * 128;
        size_t krow0 = (size_t)(b * SS + kb);
        #pragma unroll
        for (int t = 0; t < 4; t++) {
            int idx = tid + t * 256;
            int row = idx >> 3, seg = idx & 7;
            uint32_t doff = (uint32_t)(row * 72 + seg * 8) * 2;
            size_t goff = (krow0 + row) * 1024 + hbase + seg * 8;
            cp16(sb + SKHI + doff, g_Khi + goff);
            cp16(sb + SKLO + doff, g_Klo + goff);
        }
        CP_COMMIT();
        #pragma unroll
        for (int t = 0; t < 8; t++) {
            int idx = tid + t * 256;
            int kr = idx & 127;
            int c4 = (idx >> 7) * 4;
            size_t goff = (krow0 + kr) * 1024 + hbase + c4;
            uint2 uh = *reinterpret_cast<const uint2*>(g_Vhi + goff);
            uint2 ul = *reinterpret_cast<const uint2*>(g_Vlo + goff);
            unsigned short hs[4] = {(unsigned short)(uh.x & 0xffff), (unsigned short)(uh.x >> 16),
                                    (unsigned short)(uh.y & 0xffff), (unsigned short)(uh.y >> 16)};
            unsigned short ls[4] = {(unsigned short)(ul.x & 0xffff), (unsigned short)(ul.x >> 16),
                                    (unsigned short)(ul.y & 0xffff), (unsigned short)(ul.y >> 16)};
            #pragma unroll
            for (int j = 0; j < 4; j++) {
                uint32_t off = (uint32_t)((c4 + j) * 136 + kr) * 2;
                sts16(sb + SVTHI + off, hs[j]);
                sts16(sb + SVTLO + off, ls[j]);
            }
        }
        CP_WAIT(0);
        __syncthreads();

        // ---- scores (3-pass) ----
        float s[16][4];
        #pragma unroll
        for (int j = 0; j < 16; j++)
            #pragma unroll
            for (int r = 0; r < 4; r++) s[j][r] = 0.f;

        #pragma unroll
        for (int ks = 0; ks < 4; ks++) {
            uint32_t qa = sb + SQHI + (uint32_t)((w*16 + lm_a)*72 + ks*16 + lm_ak)*2;
            uint32_t qh[4], ql[4];
            ldsm4(qh, qa);
            ldsm4(ql, qa + (SQLO - SQHI));
            #pragma unroll
            for (int jp = 0; jp < 8; jp++) {
                uint32_t ka = sb + SKHI + (uint32_t)((jp*16 + lm_bn)*72 + ks*16 + lm_bk)*2;
                uint32_t kh[4], kl[4];
                ldsm4(kh, ka);
                ldsm4(kl, ka + (SKLO - SKHI));
                mma_f16(s[2*jp],   qh, kh[0], kh[1]);
                mma_f16(s[2*jp],   qh, kl[0], kl[1]);
                mma_f16(s[2*jp],   ql, kh[0], kh[1]);
                mma_f16(s[2*jp+1], qh, kh[2], kh[3]);
                mma_f16(s[2*jp+1], qh, kl[2], kl[3]);
                mma_f16(s[2*jp+1], ql, kh[2], kh[3]);
            }
        }

        // ---- bias + online softmax ----
        int qrel0 = w*16 + g;
        #pragma unroll
        for (int j = 0; j < 16; j++) {
            int idx0 = kb + j*8 + t2 - qrel0 + 127;
            s[j][0] += sbias[idx0];
            s[j][1] += sbias[idx0 + 1];
            s[j][2] += sbias[idx0 - 8];
            s[j][3] += sbias[idx0 - 7];
        }
        float mx0 = -1e30f, mx1 = -1e30f;
        #pragma unroll
        for (int j = 0; j < 16; j++) {
            mx0 = fmaxf(mx0, fmaxf(s[j][0], s[j][1]));
            mx1 = fmaxf(mx1, fmaxf(s[j][2], s[j][3]));
        }
        mx0 = fmaxf(mx0, __shfl_xor_sync(0xffffffffu, mx0, 1));
        mx0 = fmaxf(mx0, __shfl_xor_sync(0xffffffffu, mx0, 2));
        mx1 = fmaxf(mx1, __shfl_xor_sync(0xffffffffu, mx1, 1));
        mx1 = fmaxf(mx1, __shfl_xor_sync(0xffffffffu, mx1, 2));
        float mn0 = fmaxf(mrow[0], mx0), mn1 = fmaxf(mrow[1], mx1);
        float f0 = __expf(mrow[0] - mn0), f1 = __expf(mrow[1] - mn1);
        float sum0 = 0.f, sum1 = 0.f;
        #pragma unroll
        for (int j = 0; j < 16; j++) {
            s[j][0] = __expf(s[j][0] - mn0);
            s[j][1] = __expf(s[j][1] - mn0);
            s[j][2] = __expf(s[j][2] - mn1);
            s[j][3] = __expf(s[j][3] - mn1);
            sum0 += s[j][0] + s[j][1];
            sum1 += s[j][2] + s[j][3];
        }
        sum0 += __shfl_xor_sync(0xffffffffu, sum0, 1);
        sum0 += __shfl_xor_sync(0xffffffffu, sum0, 2);
        sum1 += __shfl_xor_sync(0xffffffffu, sum1, 1);
        sum1 += __shfl_xor_sync(0xffffffffu, sum1, 2);
        lrow[0] = lrow[0]*f0 + sum0;
        lrow[1] = lrow[1]*f1 + sum1;
        mrow[0] = mn0; mrow[1] = mn1;
        #pragma unroll
        for (int jn = 0; jn < 8; jn++) {
            acc[jn][0] *= f0; acc[jn][1] *= f0;
            acc[jn][2] *= f1; acc[jn][3] *= f1;
        }

        // ---- PV (2-pass: ph*vh + ph*vl) ----
        #pragma unroll
        for (int kk = 0; kk < 8; kk++) {
            int j0 = 2*kk, j1 = 2*kk + 1;
            uint32_t ph[4];
            ph[0] = packh(s[j0][0], s[j0][1]);
            ph[1] = packh(s[j0][2], s[j0][3]);
            ph[2] = packh(s[j1][0], s[j1][1]);
            ph[3] = packh(s[j1][2], s[j1][3]);
            #pragma unroll
            for (int jp = 0; jp < 4; jp++) {
                uint32_t va = sb + SVTHI + (uint32_t)((jp*16 + lm_bn)*136 + kk*16 + lm_bk)*2;
                uint32_t vh[4], vl[4];
                ldsm4(vh, va);
                ldsm4(vl, va + (SVTLO - SVTHI));
                mma_f16(acc[2*jp],   ph, vh[0], vh[1]);
                mma_f16(acc[2*jp],   ph, vl[0], vl[1]);
                mma_f16(acc[2*jp+1], ph, vh[2], vh[3]);
                mma_f16(acc[2*jp+1], ph, vl[2], vl[3]);
            }
        }
    }

    // ---- epilogue: ctx hi/lo ----
    float i0 = 1.0f / lrow[0], i1 = 1.0f / lrow[1];
    size_t r0 = qrow0 + w*16 + g;
    #pragma unroll
    for (int jn = 0; jn < 8; jn++) {
        int n = hbase + jn*8 + t2;
        uint32_t lo0, lo1;
        uint32_t h0 = packpair(acc[jn][0]*i0, acc[jn][1]*i0, lo0);
        uint32_t h1 = packpair(acc[jn][2]*i1, acc[jn][3]*i1, lo1);
        *reinterpret_cast<uint32_t*>(&g_chi[r0*1024 + n])       = h0;
        *reinterpret_cast<uint32_t*>(&g_clo[r0*1024 + n])       = lo0;
        *reinterpret_cast<uint32_t*>(&g_chi[(r0+8)*1024 + n])   = h1;
        *reinterpret_cast<uint32_t*>(&g_clo[(r0+8)*1024 + n])   = lo1;
    }
}

// ---------------- launch ----------------
extern "C" void kernel_launch(void* const* d_in, const int* in_sizes, int n_in,
                              void* d_out, int out_size)
{
    const float* hidden = (const float*)d_in[0];
    const float* Wq     = (const float*)d_in[1];
    const float* Wk     = (const float*)d_in[2];
    const float* Wv     = (const float*)d_in[3];
    const float* Wo     = (const float*)d_in[4];
    const float* tbl    = (const float*)d_in[5];
    float* out = (float*)d_out;
    (void)in_sizes; (void)n_in;

    h16 *phhi, *phlo, *pWthi, *pWtlo, *pQhi, *pQlo, *pKhi, *pKlo, *pVhi, *pVlo, *pchi, *pclo;
    cudaGetSymbolAddress((void**)&phhi, g_hhi);
    cudaGetSymbolAddress((void**)&phlo, g_hlo);
    cudaGetSymbolAddress((void**)&pWthi, g_Wthi);
    cudaGetSymbolAddress((void**)&pWtlo, g_Wtlo);
    cudaGetSymbolAddress((void**)&pQhi, g_Qhi);
    cudaGetSymbolAddress((void**)&pQlo, g_Qlo);
    cudaGetSymbolAddress((void**)&pKhi, g_Khi);
    cudaGetSymbolAddress((void**)&pKlo, g_Klo);
    cudaGetSymbolAddress((void**)&pVhi, g_Vhi);
    cudaGetSymbolAddress((void**)&pVlo, g_Vlo);
    cudaGetSymbolAddress((void**)&pchi, g_chi);
    cudaGetSymbolAddress((void**)&pclo, g_clo);

    cudaFuncSetAttribute(gemm_mma_kernel,
                         cudaFuncAttributeMaxDynamicSharedMemorySize, GEMM_SMEM);
    cudaFuncSetAttribute(flash_mma_kernel,
                         cudaFuncAttributeMaxDynamicSharedMemorySize, FL_SMEM);

    const size_t WSLOT = (size_t)DDIM * DDIM;
    int n4 = MROWS * DDIM / 4;
    long long attn_elems = (long long)MROWS * DDIM;
    long long bias_elems = (long long)HH * SS * SS;

    // 1. bias table (needed by flash)
    bias_precompute_kernel<<<16, 256>>>(tbl);
    // 2. hidden split
    split_kernel<<<(n4 + 255) / 256, 256>>>(hidden, phhi, phlo, n4);
    // 3. fused W transpose+split
    wsplit4_kernel<<<dim3(32, 32, 4), dim3(32, 8)>>>(Wq, Wk, Wv, Wo, pWthi, pWtlo);
    // 4. fused Q/K/V projections (3-pass)
    gemm_mma_kernel<<<dim3(8, 32, 3), 256, GEMM_SMEM>>>(
        phhi, phlo, pWthi, pWtlo,
        pQhi, pQlo, pKhi, pKlo, pVhi, pVlo, nullptr, 0);
    // 5. flash attention
    dim3 fgrid(SS/128, BB*HH);
    flash_mma_kernel<<<fgrid, 256, FL_SMEM>>>();
    // 6. output projection (2-pass) -> fp32 out
    gemm_mma_kernel<<<dim3(8, 32, 1), 256, GEMM_SMEM>>>(
        pchi, pclo, pWthi + 3*WSLOT, pWtlo + 3*WSLOT,
        nullptr, nullptr, nullptr, nullptr, nullptr, nullptr, out, 1);
    // 7. position_bias
    if ((long long)out_size >= attn_elems + bias_elems) {
        int nblocks = (int)(bias_elems / 4 / 256);
        bias_out_kernel<<<nblocks, 256>>>(out + attn_elems);
    }
}